// round 9
// baseline (speedup 1.0000x reference)
#include <cuda_runtime.h>
#include <cuda_fp16.h>
#include <cstdint>

#define NN        2048
#define GRID      1024
#define MEM       32
#define HID       256
#define W1S_STRIDE 260   // words; 1040B row, conflict-free fragment gathers

// dynamic smem layout (bytes)
#define OFF_W1S   0
#define SZ_W1S    (32 * W1S_STRIDE * 4)          // 33280
#define OFF_XF    SZ_W1S                         // 33280
#define SZ_XF     (2048 * 4)                     // 8192
#define OFF_PART  (OFF_XF + SZ_XF)               // 41472
#define SZ_PART   (8 * 256 * 4)                  // 8192
#define SMEM_TOTAL (OFF_PART + SZ_PART)          // 49664

// precise sigmoid (epilogue only)
__device__ __forceinline__ float sigmoidf_acc(float x) {
    return __fdividef(1.0f, 1.0f + __expf(-x));
}
// fast sigmoid via MUFU.TANH (GLU1)
__device__ __forceinline__ float sigmoidf_tanh(float x) {
    float t;
    asm("tanh.approx.f32 %0, %1;" : "=f"(t) : "f"(0.5f * x));
    return fmaf(0.5f, t, 0.5f);
}

__device__ __forceinline__ void mma_f16(float c[4],
                                        uint32_t a0, uint32_t a1, uint32_t a2, uint32_t a3,
                                        uint32_t b0, uint32_t b1) {
    asm volatile(
        "mma.sync.aligned.m16n8k16.row.col.f32.f16.f16.f32 "
        "{%0,%1,%2,%3}, {%4,%5,%6,%7}, {%8,%9}, {%0,%1,%2,%3};"
        : "+f"(c[0]), "+f"(c[1]), "+f"(c[2]), "+f"(c[3])
        : "r"(a0), "r"(a1), "r"(a2), "r"(a3), "r"(b0), "r"(b1));
}

__device__ __forceinline__ uint32_t pack16(float x, float y) {
    half2 h = __floats2half2_rn(x, y);
    return *reinterpret_cast<uint32_t*>(&h);
}

__device__ __forceinline__ void cp16(uint32_t dst, const void* src) {
    asm volatile("cp.async.cg.shared.global [%0], [%1], 16;" :: "r"(dst), "l"(src));
}

__device__ __forceinline__ void issue_w1(uint32_t sbase, int n, int tid,
                                         const float* __restrict__ w1) {
    const float* W1g = w1 + (size_t)n * (MEM * HID);
    #pragma unroll
    for (int i = 0; i < 8; i++) {
        const int t  = tid + i * 256;
        const int c4 = t & 63;
        const int k  = t >> 6;
        cp16(sbase + OFF_W1S + (k * W1S_STRIDE + 4 * c4) * 4, W1g + k * HID + 4 * c4);
    }
    asm volatile("cp.async.commit_group;");
}

__global__ __launch_bounds__(256, 4)
void nlm_kernel(const float* __restrict__ state,   // (128, 2048, 32)
                const float* __restrict__ w1,      // (2048, 32, 256)
                const float* __restrict__ b1,      // (2048, 256)
                const float* __restrict__ w2,      // (2048, 128, 2)
                const float* __restrict__ b2,      // (2048, 2)
                const float* __restrict__ Tg,      // (1,)
                float* __restrict__ out)           // (128, 2048)
{
    extern __shared__ char smem[];
    const uint32_t sbase = (uint32_t)__cvta_generic_to_shared(smem);
    float*    W1s  = (float*)(smem + OFF_W1S);
    uint32_t* XF   = (uint32_t*)(smem + OFF_XF);
    float*    part = (float*)(smem + OFF_PART);

    const int bid  = blockIdx.x;
    const int tid  = threadIdx.x;
    const int w    = tid >> 5;     // warp 0..7, owns GLU pair-tiles {2w, 2w+1}
    const int lane = tid & 31;
    const int q    = lane & 3;
    const int lr   = lane >> 2;

    // prologue: start W1 stream for first neuron
    issue_w1(sbase, bid, tid, w1);

    #pragma unroll
    for (int it = 0; it < 2; it++) {
        const int n = bid + GRID * it;

        // ---- X: 4 x LDG.128 per thread -> fp16 fragments ----
        // (iter 0: XF untouched yet; iter 1: previous mainloop XF reads are
        //  fenced by the post-mainloop __syncthreads)
        const float* Xg = state + (size_t)n * MEM;
        #pragma unroll
        for (int i = 0; i < 4; i++) {
            const int t    = tid + i * 256;
            const int s    = t & 7;
            const int brow = t >> 3;
            const float4 v = *reinterpret_cast<const float4*>(Xg + (size_t)brow * (NN * MEM) + 4 * s);
            const int p0   = 2 * s;
            const int q0   = p0 & 3;
            const int reg2 = (p0 >> 2) & 1;
            const int ks   = p0 >> 3;
            const int flr  = brow & 7;
            const int reg  = ((brow >> 3) & 1) + 2 * reg2;
            const int m    = brow >> 4;
            const int base = ((m * 2 + ks) * 32 + flr * 4) * 4 + reg;
            XF[base + q0 * 4]       = pack16(v.x, v.y);
            XF[base + (q0 + 1) * 4] = pack16(v.z, v.w);
        }

        // per-warp bias / W2 registers
        const int h0 = (2 * w) * 8 + 2 * q;
        const float2 ba0 = *reinterpret_cast<const float2*>(&b1[n * 256 + h0]);
        const float2 bb0 = *reinterpret_cast<const float2*>(&b1[n * 256 + 128 + h0]);
        const float2 ba1 = *reinterpret_cast<const float2*>(&b1[n * 256 + h0 + 8]);
        const float2 bb1 = *reinterpret_cast<const float2*>(&b1[n * 256 + 136 + h0]);
        const float4 w2f0 = *reinterpret_cast<const float4*>(&w2[n * 256 + h0 * 2]);
        const float4 w2f1 = *reinterpret_cast<const float4*>(&w2[n * 256 + (h0 + 8) * 2]);

        asm volatile("cp.async.wait_group 0;");
        __syncthreads();

        // ---- build W1 fp16 fragments (conflict-free gathers) ----
        uint32_t BA[2][2][2], BB[2][2][2];
        #pragma unroll
        for (int p = 0; p < 2; p++) {
            const int colA = (2 * w + p) * 8 + lr;
            const int colB = colA + 128;
            #pragma unroll
            for (int ks = 0; ks < 2; ks++) {
                #pragma unroll
                for (int r = 0; r < 2; r++) {
                    const int k = ks * 16 + r * 8 + 2 * q;
                    BA[p][ks][r] = pack16(W1s[k * W1S_STRIDE + colA], W1s[(k + 1) * W1S_STRIDE + colA]);
                    BB[p][ks][r] = pack16(W1s[k * W1S_STRIDE + colB], W1s[(k + 1) * W1S_STRIDE + colB]);
                }
            }
        }
        __syncthreads();   // all warps done reading W1s

        // pipeline: stream next neuron's W1 during mainloop + epilogue
        if (it == 0)
            issue_w1(sbase, bid + GRID, tid, w1);

        // ---- mainloop over 8 M-tiles ----
        float* myPart = part + w * 256;
        #pragma unroll
        for (int m = 0; m < 8; m++) {
            const uint4 A0 = *reinterpret_cast<const uint4*>(&XF[((m * 2 + 0) * 32 + lane) * 4]);
            const uint4 A1 = *reinterpret_cast<const uint4*>(&XF[((m * 2 + 1) * 32 + lane) * 4]);

            float accLo0, accLo1, accHi0, accHi1;
            {
                float Ca[4] = {ba0.x, ba0.y, ba0.x, ba0.y};
                float Cb[4] = {bb0.x, bb0.y, bb0.x, bb0.y};
                mma_f16(Ca, A0.x, A0.y, A0.z, A0.w, BA[0][0][0], BA[0][0][1]);
                mma_f16(Cb, A0.x, A0.y, A0.z, A0.w, BB[0][0][0], BB[0][0][1]);
                mma_f16(Ca, A1.x, A1.y, A1.z, A1.w, BA[0][1][0], BA[0][1][1]);
                mma_f16(Cb, A1.x, A1.y, A1.z, A1.w, BB[0][1][0], BB[0][1][1]);
                const float g0 = Ca[0] * sigmoidf_tanh(Cb[0]);
                const float g1 = Ca[1] * sigmoidf_tanh(Cb[1]);
                const float g2 = Ca[2] * sigmoidf_tanh(Cb[2]);
                const float g3 = Ca[3] * sigmoidf_tanh(Cb[3]);
                accLo0 = g0 * w2f0.x + g1 * w2f0.z;
                accLo1 = g0 * w2f0.y + g1 * w2f0.w;
                accHi0 = g2 * w2f0.x + g3 * w2f0.z;
                accHi1 = g2 * w2f0.y + g3 * w2f0.w;
            }
            {
                float Ca[4] = {ba1.x, ba1.y, ba1.x, ba1.y};
                float Cb[4] = {bb1.x, bb1.y, bb1.x, bb1.y};
                mma_f16(Ca, A0.x, A0.y, A0.z, A0.w, BA[1][0][0], BA[1][0][1]);
                mma_f16(Cb, A0.x, A0.y, A0.z, A0.w, BB[1][0][0], BB[1][0][1]);
                mma_f16(Ca, A1.x, A1.y, A1.z, A1.w, BA[1][1][0], BA[1][1][1]);
                mma_f16(Cb, A1.x, A1.y, A1.z, A1.w, BB[1][1][0], BB[1][1][1]);
                const float g0 = Ca[0] * sigmoidf_tanh(Cb[0]);
                const float g1 = Ca[1] * sigmoidf_tanh(Cb[1]);
                const float g2 = Ca[2] * sigmoidf_tanh(Cb[2]);
                const float g3 = Ca[3] * sigmoidf_tanh(Cb[3]);
                accLo0 += g0 * w2f1.x + g1 * w2f1.z;
                accLo1 += g0 * w2f1.y + g1 * w2f1.w;
                accHi0 += g2 * w2f1.x + g3 * w2f1.z;
                accHi1 += g2 * w2f1.y + g3 * w2f1.w;
            }

            // butterfly-with-rotation quad reduction: 3 SHFL + 1 STS
            float a = (q & 1) ? accLo1 : accLo0;
            float b = (q & 1) ? accLo0 : accLo1;
            float c = (q & 1) ? accHi1 : accHi0;
            float d = (q & 1) ? accHi0 : accHi1;
            a += __shfl_xor_sync(0xffffffffu, b, 1);
            c += __shfl_xor_sync(0xffffffffu, d, 1);
            float u = (q & 2) ? c : a;
            float v = (q & 2) ? a : c;
            u += __shfl_xor_sync(0xffffffffu, v, 2);
            const int row = m * 16 + lr + ((q & 2) << 2);
            myPart[row * 2 + (q & 1)] = u;
        }

        __syncthreads();

        // ---- final: sum 8 warp partials, GLU2 (precise), /T, store ----
        if (tid < 128) {
            const float2 b2v = *reinterpret_cast<const float2*>(&b2[n * 2]);
            float y0 = b2v.x;
            float y1 = b2v.y;
            #pragma unroll
            for (int ww = 0; ww < 8; ww++) {
                const float2 pv = *reinterpret_cast<const float2*>(&part[ww * 256 + tid * 2]);
                y0 += pv.x;
                y1 += pv.y;
            }
            out[(size_t)tid * NN + n] = (y0 * sigmoidf_acc(y1)) / Tg[0];
        }
        // iter-1 part writes are fenced by two syncthreads in its prologue
    }
}

extern "C" void kernel_launch(void* const* d_in, const int* in_sizes, int n_in,
                              void* d_out, int out_size) {
    const float* state = (const float*)d_in[0];
    const float* w1    = (const float*)d_in[1];
    const float* b1    = (const float*)d_in[2];
    const float* w2    = (const float*)d_in[3];
    const float* b2    = (const float*)d_in[4];
    const float* T     = (const float*)d_in[5];
    float* out = (float*)d_out;
    cudaFuncSetAttribute(nlm_kernel, cudaFuncAttributeMaxDynamicSharedMemorySize, SMEM_TOTAL);
    nlm_kernel<<<GRID, 256, SMEM_TOTAL>>>(state, w1, b1, w2, b2, T, out);
}

// round 10
// speedup vs baseline: 1.1280x; 1.1280x over previous
#include <cuda_runtime.h>
#include <cuda_fp16.h>
#include <cstdint>

#define NN        2048
#define MEM       32
#define HID       256
#define W1S_STRIDE 260   // words; 1040B row, conflict-free fragment gathers

// dynamic smem layout (bytes)
#define OFF_W1S   0
#define SZ_W1S    (32 * W1S_STRIDE * 4)          // 33280
#define OFF_XF    SZ_W1S                         // 33280
#define SZ_XF     (2048 * 4)                     // 8192
#define OFF_PART  (OFF_XF + SZ_XF)               // 41472
#define SZ_PART   (8 * 256 * 4)                  // 8192
#define SMEM_TOTAL (OFF_PART + SZ_PART)          // 49664

// precise sigmoid (epilogue only)
__device__ __forceinline__ float sigmoidf_acc(float x) {
    return __fdividef(1.0f, 1.0f + __expf(-x));
}
// fast sigmoid from PRE-HALVED argument: sigma(2*xh) = 0.5*tanh(xh)+0.5
__device__ __forceinline__ float sigmoid_from_half(float xh) {
    float t;
    asm("tanh.approx.f32 %0, %1;" : "=f"(t) : "f"(xh));
    return fmaf(0.5f, t, 0.5f);
}

__device__ __forceinline__ void mma_f16(float c[4],
                                        uint32_t a0, uint32_t a1, uint32_t a2, uint32_t a3,
                                        uint32_t b0, uint32_t b1) {
    asm volatile(
        "mma.sync.aligned.m16n8k16.row.col.f32.f16.f16.f32 "
        "{%0,%1,%2,%3}, {%4,%5,%6,%7}, {%8,%9}, {%0,%1,%2,%3};"
        : "+f"(c[0]), "+f"(c[1]), "+f"(c[2]), "+f"(c[3])
        : "r"(a0), "r"(a1), "r"(a2), "r"(a3), "r"(b0), "r"(b1));
}

__device__ __forceinline__ uint32_t pack16(float x, float y) {
    half2 h = __floats2half2_rn(x, y);
    return *reinterpret_cast<uint32_t*>(&h);
}

__device__ __forceinline__ void cp16(uint32_t dst, const void* src) {
    asm volatile("cp.async.cg.shared.global [%0], [%1], 16;" :: "r"(dst), "l"(src));
}

__global__ __launch_bounds__(256, 3)
void nlm_kernel(const float* __restrict__ state,   // (128, 2048, 32)
                const float* __restrict__ w1,      // (2048, 32, 256)
                const float* __restrict__ b1,      // (2048, 256)
                const float* __restrict__ w2,      // (2048, 128, 2)
                const float* __restrict__ b2,      // (2048, 2)
                const float* __restrict__ Tg,      // (1,)
                float* __restrict__ out)           // (128, 2048)
{
    extern __shared__ char smem[];
    const uint32_t sbase = (uint32_t)__cvta_generic_to_shared(smem);
    float*    W1s  = (float*)(smem + OFF_W1S);
    uint32_t* XF   = (uint32_t*)(smem + OFF_XF);
    float*    part = (float*)(smem + OFF_PART);

    const int n    = blockIdx.x;
    const int tid  = threadIdx.x;
    const int w    = tid >> 5;     // warp 0..7, owns GLU pair-tiles {2w, 2w+1}
    const int lane = tid & 31;
    const int q    = lane & 3;
    const int lr   = lane >> 2;

    // ---------------- Prologue ----------------
    // bias / W2 loads first (long latency, consumed after build)
    const int h0 = (2 * w) * 8 + 2 * q;                 // first tile's g-col (even)
    const float2 ba0 = *reinterpret_cast<const float2*>(&b1[n * 256 + h0]);
    const float2 bbr0 = *reinterpret_cast<const float2*>(&b1[n * 256 + 128 + h0]);
    const float2 ba1 = *reinterpret_cast<const float2*>(&b1[n * 256 + h0 + 8]);
    const float2 bbr1 = *reinterpret_cast<const float2*>(&b1[n * 256 + 136 + h0]);
    const float4 w2f0 = *reinterpret_cast<const float4*>(&w2[n * 256 + h0 * 2]);
    const float4 w2f1 = *reinterpret_cast<const float4*>(&w2[n * 256 + (h0 + 8) * 2]);
    // halved gate biases (0.5 folded into gate-side path; exact scaling)
    const float2 bb0 = make_float2(0.5f * bbr0.x, 0.5f * bbr0.y);
    const float2 bb1 = make_float2(0.5f * bbr1.x, 0.5f * bbr1.y);

    const float* W1g = w1 + (size_t)n * (MEM * HID);
    #pragma unroll
    for (int i = 0; i < 8; i++) {
        const int t  = tid + i * 256;
        const int c4 = t & 63;
        const int k  = t >> 6;
        cp16(sbase + OFF_W1S + (k * W1S_STRIDE + 4 * c4) * 4, W1g + k * HID + 4 * c4);
    }
    asm volatile("cp.async.commit_group;");

    // X: 4 x LDG.128 per thread -> fp16 fragments
    const float* Xg = state + (size_t)n * MEM;
    #pragma unroll
    for (int i = 0; i < 4; i++) {
        const int t    = tid + i * 256;
        const int s    = t & 7;          // float4 index in row (k0 = 4s)
        const int brow = t >> 3;         // batch row
        const float4 v = *reinterpret_cast<const float4*>(Xg + (size_t)brow * (NN * MEM) + 4 * s);
        const int p0   = 2 * s;
        const int q0   = p0 & 3;
        const int reg2 = (p0 >> 2) & 1;
        const int ks   = p0 >> 3;
        const int flr  = brow & 7;
        const int reg  = ((brow >> 3) & 1) + 2 * reg2;
        const int m    = brow >> 4;
        const int base = ((m * 2 + ks) * 32 + flr * 4) * 4 + reg;
        XF[base + q0 * 4]       = pack16(v.x, v.y);
        XF[base + (q0 + 1) * 4] = pack16(v.z, v.w);
    }

    asm volatile("cp.async.wait_group 0;");
    __syncthreads();

    // ---------------- Build W1 fp16 fragments (gate side pre-scaled by 0.5) ----------------
    uint32_t BA[2][2][2], BB[2][2][2];
    #pragma unroll
    for (int p = 0; p < 2; p++) {
        const int colA = (2 * w + p) * 8 + lr;
        const int colB = colA + 128;
        #pragma unroll
        for (int ks = 0; ks < 2; ks++) {
            #pragma unroll
            for (int r = 0; r < 2; r++) {
                const int k = ks * 16 + r * 8 + 2 * q;
                BA[p][ks][r] = pack16(W1s[k * W1S_STRIDE + colA], W1s[(k + 1) * W1S_STRIDE + colA]);
                BB[p][ks][r] = pack16(0.5f * W1s[k * W1S_STRIDE + colB],
                                      0.5f * W1s[(k + 1) * W1S_STRIDE + colB]);
            }
        }
    }

    // ---------------- Mainloop over 8 M-tiles ----------------
    float* myPart = part + w * 256;
    #pragma unroll
    for (int m = 0; m < 8; m++) {
        const uint4 A0 = *reinterpret_cast<const uint4*>(&XF[((m * 2 + 0) * 32 + lane) * 4]);
        const uint4 A1 = *reinterpret_cast<const uint4*>(&XF[((m * 2 + 1) * 32 + lane) * 4]);

        float accLo0, accLo1, accHi0, accHi1;
        {
            float Ca[4] = {ba0.x, ba0.y, ba0.x, ba0.y};
            float Cb[4] = {bb0.x, bb0.y, bb0.x, bb0.y};
            mma_f16(Ca, A0.x, A0.y, A0.z, A0.w, BA[0][0][0], BA[0][0][1]);
            mma_f16(Cb, A0.x, A0.y, A0.z, A0.w, BB[0][0][0], BB[0][0][1]);
            mma_f16(Ca, A1.x, A1.y, A1.z, A1.w, BA[0][1][0], BA[0][1][1]);
            mma_f16(Cb, A1.x, A1.y, A1.z, A1.w, BB[0][1][0], BB[0][1][1]);
            const float g0 = Ca[0] * sigmoid_from_half(Cb[0]);
            const float g1 = Ca[1] * sigmoid_from_half(Cb[1]);
            const float g2 = Ca[2] * sigmoid_from_half(Cb[2]);
            const float g3 = Ca[3] * sigmoid_from_half(Cb[3]);
            accLo0 = g0 * w2f0.x + g1 * w2f0.z;
            accLo1 = g0 * w2f0.y + g1 * w2f0.w;
            accHi0 = g2 * w2f0.x + g3 * w2f0.z;
            accHi1 = g2 * w2f0.y + g3 * w2f0.w;
        }
        {
            float Ca[4] = {ba1.x, ba1.y, ba1.x, ba1.y};
            float Cb[4] = {bb1.x, bb1.y, bb1.x, bb1.y};
            mma_f16(Ca, A0.x, A0.y, A0.z, A0.w, BA[1][0][0], BA[1][0][1]);
            mma_f16(Cb, A0.x, A0.y, A0.z, A0.w, BB[1][0][0], BB[1][0][1]);
            mma_f16(Ca, A1.x, A1.y, A1.z, A1.w, BA[1][1][0], BA[1][1][1]);
            mma_f16(Cb, A1.x, A1.y, A1.z, A1.w, BB[1][1][0], BB[1][1][1]);
            const float g0 = Ca[0] * sigmoid_from_half(Cb[0]);
            const float g1 = Ca[1] * sigmoid_from_half(Cb[1]);
            const float g2 = Ca[2] * sigmoid_from_half(Cb[2]);
            const float g3 = Ca[3] * sigmoid_from_half(Cb[3]);
            accLo0 += g0 * w2f1.x + g1 * w2f1.z;
            accLo1 += g0 * w2f1.y + g1 * w2f1.w;
            accHi0 += g2 * w2f1.x + g3 * w2f1.z;
            accHi1 += g2 * w2f1.y + g3 * w2f1.w;
        }

        // butterfly-with-rotation quad reduction: 3 SHFL + 1 STS
        float a = (q & 1) ? accLo1 : accLo0;
        float b = (q & 1) ? accLo0 : accLo1;
        float c = (q & 1) ? accHi1 : accHi0;
        float d = (q & 1) ? accHi0 : accHi1;
        a += __shfl_xor_sync(0xffffffffu, b, 1);
        c += __shfl_xor_sync(0xffffffffu, d, 1);
        float u = (q & 2) ? c : a;
        float v = (q & 2) ? a : c;
        u += __shfl_xor_sync(0xffffffffu, v, 2);
        const int row = m * 16 + lr + ((q & 2) << 2);
        myPart[row * 2 + (q & 1)] = u;
    }

    __syncthreads();

    // ---------------- Final: sum 8 warp partials, GLU2 (precise), /T, store ----------------
    if (tid < 128) {
        const float2 b2v = *reinterpret_cast<const float2*>(&b2[n * 2]);
        float y0 = b2v.x;
        float y1 = b2v.y;
        #pragma unroll
        for (int ww = 0; ww < 8; ww++) {
            const float2 pv = *reinterpret_cast<const float2*>(&part[ww * 256 + tid * 2]);
            y0 += pv.x;
            y1 += pv.y;
        }
        out[(size_t)tid * NN + n] = (y0 * sigmoidf_acc(y1)) / Tg[0];
    }
}

extern "C" void kernel_launch(void* const* d_in, const int* in_sizes, int n_in,
                              void* d_out, int out_size) {
    const float* state = (const float*)d_in[0];
    const float* w1    = (const float*)d_in[1];
    const float* b1    = (const float*)d_in[2];
    const float* w2    = (const float*)d_in[3];
    const float* b2    = (const float*)d_in[4];
    const float* T     = (const float*)d_in[5];
    float* out = (float*)d_out;
    cudaFuncSetAttribute(nlm_kernel, cudaFuncAttributeMaxDynamicSharedMemorySize, SMEM_TOTAL);
    nlm_kernel<<<NN, 256, SMEM_TOTAL>>>(state, w1, b1, w2, b2, T, out);
}

// round 11
// speedup vs baseline: 1.2171x; 1.0789x over previous
#include <cuda_runtime.h>
#include <cuda_fp16.h>
#include <cstdint>

#define NN        2048
#define MEM       32
#define HID       256
#define W1S_STRIDE 260   // words; 1040B row, conflict-free fragment gathers

// dynamic smem layout (bytes)
#define OFF_W1S   0
#define SZ_W1S    (32 * W1S_STRIDE * 4)          // 33280
#define OFF_XF    SZ_W1S                         // 33280
#define SZ_XF     (2048 * 4)                     // 8192
#define OFF_PART  (OFF_XF + SZ_XF)               // 41472
#define SZ_PART   (8 * 256 * 4)                  // 8192
#define SMEM_TOTAL (OFF_PART + SZ_PART)          // 49664

// precise sigmoid (epilogue only)
__device__ __forceinline__ float sigmoidf_acc(float x) {
    return __fdividef(1.0f, 1.0f + __expf(-x));
}
// fast sigmoid from PRE-HALVED argument: sigma(2*xh) = 0.5*tanh(xh)+0.5
__device__ __forceinline__ float sigmoid_from_half(float xh) {
    float t;
    asm("tanh.approx.f32 %0, %1;" : "=f"(t) : "f"(xh));
    return fmaf(0.5f, t, 0.5f);
}

__device__ __forceinline__ void mma_f16(float c[4],
                                        uint32_t a0, uint32_t a1, uint32_t a2, uint32_t a3,
                                        uint32_t b0, uint32_t b1) {
    asm volatile(
        "mma.sync.aligned.m16n8k16.row.col.f32.f16.f16.f32 "
        "{%0,%1,%2,%3}, {%4,%5,%6,%7}, {%8,%9}, {%0,%1,%2,%3};"
        : "+f"(c[0]), "+f"(c[1]), "+f"(c[2]), "+f"(c[3])
        : "r"(a0), "r"(a1), "r"(a2), "r"(a3), "r"(b0), "r"(b1));
}

__device__ __forceinline__ uint32_t pack16(float x, float y) {
    half2 h = __floats2half2_rn(x, y);
    return *reinterpret_cast<uint32_t*>(&h);
}

__device__ __forceinline__ void cp16(uint32_t dst, const void* src) {
    asm volatile("cp.async.cg.shared.global [%0], [%1], 16;" :: "r"(dst), "l"(src));
}

__global__ __launch_bounds__(256, 4)
void nlm_kernel(const float* __restrict__ state,   // (128, 2048, 32)
                const float* __restrict__ w1,      // (2048, 32, 256)
                const float* __restrict__ b1,      // (2048, 256)
                const float* __restrict__ w2,      // (2048, 128, 2)
                const float* __restrict__ b2,      // (2048, 2)
                const float* __restrict__ Tg,      // (1,)
                float* __restrict__ out)           // (128, 2048)
{
    extern __shared__ char smem[];
    const uint32_t sbase = (uint32_t)__cvta_generic_to_shared(smem);
    float*    W1s  = (float*)(smem + OFF_W1S);
    uint32_t* XF   = (uint32_t*)(smem + OFF_XF);
    float*    part = (float*)(smem + OFF_PART);

    const int n    = blockIdx.x;
    const int tid  = threadIdx.x;
    const int w    = tid >> 5;     // warp 0..7, owns GLU pair-tiles {2w, 2w+1}
    const int lane = tid & 31;
    const int q    = lane & 3;
    const int lr   = lane >> 2;

    // ---------------- Prologue ----------------
    // bias / W2 loads first (long scoreboard hidden under the cp.async wait)
    const int h0 = (2 * w) * 8 + 2 * q;                 // first tile's g-col (even)
    const float2 ba0  = *reinterpret_cast<const float2*>(&b1[n * 256 + h0]);
    const float2 bbr0 = *reinterpret_cast<const float2*>(&b1[n * 256 + 128 + h0]);
    const float2 ba1  = *reinterpret_cast<const float2*>(&b1[n * 256 + h0 + 8]);
    const float2 bbr1 = *reinterpret_cast<const float2*>(&b1[n * 256 + 136 + h0]);
    const float4 w2f0 = *reinterpret_cast<const float4*>(&w2[n * 256 + h0 * 2]);
    const float4 w2f1 = *reinterpret_cast<const float4*>(&w2[n * 256 + (h0 + 8) * 2]);

    const float* W1g = w1 + (size_t)n * (MEM * HID);
    #pragma unroll
    for (int i = 0; i < 8; i++) {
        const int t  = tid + i * 256;
        const int c4 = t & 63;
        const int k  = t >> 6;
        cp16(sbase + OFF_W1S + (k * W1S_STRIDE + 4 * c4) * 4, W1g + k * HID + 4 * c4);
    }
    asm volatile("cp.async.commit_group;");

    // X: 4 x LDG.128 per thread -> fp16 fragments
    const float* Xg = state + (size_t)n * MEM;
    #pragma unroll
    for (int i = 0; i < 4; i++) {
        const int t    = tid + i * 256;
        const int s    = t & 7;          // float4 index in row (k0 = 4s)
        const int brow = t >> 3;         // batch row
        const float4 v = *reinterpret_cast<const float4*>(Xg + (size_t)brow * (NN * MEM) + 4 * s);
        const int p0   = 2 * s;
        const int q0   = p0 & 3;
        const int reg2 = (p0 >> 2) & 1;
        const int ks   = p0 >> 3;
        const int flr  = brow & 7;
        const int reg  = ((brow >> 3) & 1) + 2 * reg2;
        const int m    = brow >> 4;
        const int base = ((m * 2 + ks) * 32 + flr * 4) * 4 + reg;
        XF[base + q0 * 4]       = pack16(v.x, v.y);
        XF[base + (q0 + 1) * 4] = pack16(v.z, v.w);
    }

    // halved gate biases (0.5 folded into gate path; exact power-of-2 scaling)
    const float2 bb0 = make_float2(0.5f * bbr0.x, 0.5f * bbr0.y);
    const float2 bb1 = make_float2(0.5f * bbr1.x, 0.5f * bbr1.y);

    asm volatile("cp.async.wait_group 0;");
    __syncthreads();

    // ---------------- Build W1 fp16 fragments (gate side pre-scaled by 0.5) ----------------
    uint32_t BA[2][2][2], BB[2][2][2];
    #pragma unroll
    for (int p = 0; p < 2; p++) {
        const int colA = (2 * w + p) * 8 + lr;
        const int colB = colA + 128;
        #pragma unroll
        for (int ks = 0; ks < 2; ks++) {
            #pragma unroll
            for (int r = 0; r < 2; r++) {
                const int k = ks * 16 + r * 8 + 2 * q;
                BA[p][ks][r] = pack16(W1s[k * W1S_STRIDE + colA], W1s[(k + 1) * W1S_STRIDE + colA]);
                BB[p][ks][r] = pack16(0.5f * W1s[k * W1S_STRIDE + colB],
                                      0.5f * W1s[(k + 1) * W1S_STRIDE + colB]);
            }
        }
    }

    // ---------------- Mainloop over 8 M-tiles ----------------
    float* myPart = part + w * 256;
    #pragma unroll
    for (int m = 0; m < 8; m++) {
        const uint4 A0 = *reinterpret_cast<const uint4*>(&XF[((m * 2 + 0) * 32 + lane) * 4]);
        const uint4 A1 = *reinterpret_cast<const uint4*>(&XF[((m * 2 + 1) * 32 + lane) * 4]);

        float accLo0, accLo1, accHi0, accHi1;
        {
            float Ca[4] = {ba0.x, ba0.y, ba0.x, ba0.y};
            float Cb[4] = {bb0.x, bb0.y, bb0.x, bb0.y};
            mma_f16(Ca, A0.x, A0.y, A0.z, A0.w, BA[0][0][0], BA[0][0][1]);
            mma_f16(Cb, A0.x, A0.y, A0.z, A0.w, BB[0][0][0], BB[0][0][1]);
            mma_f16(Ca, A1.x, A1.y, A1.z, A1.w, BA[0][1][0], BA[0][1][1]);
            mma_f16(Cb, A1.x, A1.y, A1.z, A1.w, BB[0][1][0], BB[0][1][1]);
            const float g0 = Ca[0] * sigmoid_from_half(Cb[0]);
            const float g1 = Ca[1] * sigmoid_from_half(Cb[1]);
            const float g2 = Ca[2] * sigmoid_from_half(Cb[2]);
            const float g3 = Ca[3] * sigmoid_from_half(Cb[3]);
            accLo0 = g0 * w2f0.x + g1 * w2f0.z;
            accLo1 = g0 * w2f0.y + g1 * w2f0.w;
            accHi0 = g2 * w2f0.x + g3 * w2f0.z;
            accHi1 = g2 * w2f0.y + g3 * w2f0.w;
        }
        {
            float Ca[4] = {ba1.x, ba1.y, ba1.x, ba1.y};
            float Cb[4] = {bb1.x, bb1.y, bb1.x, bb1.y};
            mma_f16(Ca, A0.x, A0.y, A0.z, A0.w, BA[1][0][0], BA[1][0][1]);
            mma_f16(Cb, A0.x, A0.y, A0.z, A0.w, BB[1][0][0], BB[1][0][1]);
            mma_f16(Ca, A1.x, A1.y, A1.z, A1.w, BA[1][1][0], BA[1][1][1]);
            mma_f16(Cb, A1.x, A1.y, A1.z, A1.w, BB[1][1][0], BB[1][1][1]);
            const float g0 = Ca[0] * sigmoid_from_half(Cb[0]);
            const float g1 = Ca[1] * sigmoid_from_half(Cb[1]);
            const float g2 = Ca[2] * sigmoid_from_half(Cb[2]);
            const float g3 = Ca[3] * sigmoid_from_half(Cb[3]);
            accLo0 += g0 * w2f1.x + g1 * w2f1.z;
            accLo1 += g0 * w2f1.y + g1 * w2f1.w;
            accHi0 += g2 * w2f1.x + g3 * w2f1.z;
            accHi1 += g2 * w2f1.y + g3 * w2f1.w;
        }

        // butterfly-with-rotation quad reduction: 3 SHFL + 1 STS
        float a = (q & 1) ? accLo1 : accLo0;
        float b = (q & 1) ? accLo0 : accLo1;
        float c = (q & 1) ? accHi1 : accHi0;
        float d = (q & 1) ? accHi0 : accHi1;
        a += __shfl_xor_sync(0xffffffffu, b, 1);
        c += __shfl_xor_sync(0xffffffffu, d, 1);
        float u = (q & 2) ? c : a;
        float v = (q & 2) ? a : c;
        u += __shfl_xor_sync(0xffffffffu, v, 2);
        const int row = m * 16 + lr + ((q & 2) << 2);
        myPart[row * 2 + (q & 1)] = u;
    }

    __syncthreads();

    // ---------------- Final: sum 8 warp partials (f32x2), GLU2 (precise), /T, store ----------------
    if (tid < 128) {
        uint64_t acc;
        {
            const float2 b2v = *reinterpret_cast<const float2*>(&b2[n * 2]);
            asm("mov.b64 %0, {%1, %2};" : "=l"(acc) : "f"(b2v.x), "f"(b2v.y));
        }
        #pragma unroll
        for (int ww = 0; ww < 8; ww++) {
            const uint64_t pv = *reinterpret_cast<const uint64_t*>(&part[ww * 256 + tid * 2]);
            asm("add.rn.f32x2 %0, %0, %1;" : "+l"(acc) : "l"(pv));
        }
        float y0, y1;
        asm("mov.b64 {%0, %1}, %2;" : "=f"(y0), "=f"(y1) : "l"(acc));
        out[(size_t)tid * NN + n] = (y0 * sigmoidf_acc(y1)) / Tg[0];
    }
}

extern "C" void kernel_launch(void* const* d_in, const int* in_sizes, int n_in,
                              void* d_out, int out_size) {
    const float* state = (const float*)d_in[0];
    const float* w1    = (const float*)d_in[1];
    const float* b1    = (const float*)d_in[2];
    const float* w2    = (const float*)d_in[3];
    const float* b2    = (const float*)d_in[4];
    const float* T     = (const float*)d_in[5];
    float* out = (float*)d_out;
    cudaFuncSetAttribute(nlm_kernel, cudaFuncAttributeMaxDynamicSharedMemorySize, SMEM_TOTAL);
    nlm_kernel<<<NN, 256, SMEM_TOTAL>>>(state, w1, b1, w2, b2, T, out);
}

// round 12
// speedup vs baseline: 1.2952x; 1.0642x over previous
#include <cuda_runtime.h>
#include <cuda_fp16.h>
#include <cstdint>

#define NN        2048
#define MEM       32
#define HID       256
#define W1S_STRIDE 260   // words; 1040B row, conflict-free fragment gathers

// dynamic smem layout (bytes)
#define OFF_W1S   0
#define SZ_W1S    (32 * W1S_STRIDE * 4)          // 33280
#define OFF_XF    SZ_W1S                         // 33280
#define SZ_XF     (2048 * 4)                     // 8192
#define OFF_PART  (OFF_XF + SZ_XF)               // 41472
#define SZ_PART   (8 * 256 * 4)                  // 8192
#define SMEM_TOTAL (OFF_PART + SZ_PART)          // 49664

// precise sigmoid (epilogue only)
__device__ __forceinline__ float sigmoidf_acc(float x) {
    return __fdividef(1.0f, 1.0f + __expf(-x));
}
// fast sigmoid from PRE-HALVED argument: sigma(2*xh) = 0.5*tanh(xh)+0.5
__device__ __forceinline__ float sigmoid_from_half(float xh) {
    float t;
    asm("tanh.approx.f32 %0, %1;" : "=f"(t) : "f"(xh));
    return fmaf(0.5f, t, 0.5f);
}

__device__ __forceinline__ void mma_f16(float c[4],
                                        uint32_t a0, uint32_t a1, uint32_t a2, uint32_t a3,
                                        uint32_t b0, uint32_t b1) {
    asm volatile(
        "mma.sync.aligned.m16n8k16.row.col.f32.f16.f16.f32 "
        "{%0,%1,%2,%3}, {%4,%5,%6,%7}, {%8,%9}, {%0,%1,%2,%3};"
        : "+f"(c[0]), "+f"(c[1]), "+f"(c[2]), "+f"(c[3])
        : "r"(a0), "r"(a1), "r"(a2), "r"(a3), "r"(b0), "r"(b1));
}

// GEMM2 MMA with zero C-init, separate D outputs
__device__ __forceinline__ void mma_f16_zc(float d[4],
                                           uint32_t a0, uint32_t a1, uint32_t a2, uint32_t a3,
                                           uint32_t b0, uint32_t b1) {
    asm volatile(
        "mma.sync.aligned.m16n8k16.row.col.f32.f16.f16.f32 "
        "{%0,%1,%2,%3}, {%4,%5,%6,%7}, {%8,%9}, {%10,%10,%10,%10};"
        : "=f"(d[0]), "=f"(d[1]), "=f"(d[2]), "=f"(d[3])
        : "r"(a0), "r"(a1), "r"(a2), "r"(a3), "r"(b0), "r"(b1), "f"(0.0f));
}

__device__ __forceinline__ uint32_t pack16(float x, float y) {
    half2 h = __floats2half2_rn(x, y);
    return *reinterpret_cast<uint32_t*>(&h);
}

__device__ __forceinline__ void cp16(uint32_t dst, const void* src) {
    asm volatile("cp.async.cg.shared.global [%0], [%1], 16;" :: "r"(dst), "l"(src));
}

__global__ __launch_bounds__(256, 4)
void nlm_kernel(const float* __restrict__ state,   // (128, 2048, 32)
                const float* __restrict__ w1,      // (2048, 32, 256)
                const float* __restrict__ b1,      // (2048, 256)
                const float* __restrict__ w2,      // (2048, 128, 2)
                const float* __restrict__ b2,      // (2048, 2)
                const float* __restrict__ Tg,      // (1,)
                float* __restrict__ out)           // (128, 2048)
{
    extern __shared__ char smem[];
    const uint32_t sbase = (uint32_t)__cvta_generic_to_shared(smem);
    float*    W1s  = (float*)(smem + OFF_W1S);
    uint32_t* XF   = (uint32_t*)(smem + OFF_XF);
    float*    part = (float*)(smem + OFF_PART);

    const int n    = blockIdx.x;
    const int tid  = threadIdx.x;
    const int w    = tid >> 5;     // warp 0..7, owns GLU pair-tiles {2w, 2w+1} = hid cols [16w,16w+16)
    const int lane = tid & 31;
    const int q    = lane & 3;
    const int lr   = lane >> 2;

    // ---------------- Prologue ----------------
    // bias loads first (long scoreboard hidden under cp.async wait)
    const int h0 = (2 * w) * 8 + 2 * q;                 // first tile's g-col (even)
    const float2 ba0  = *reinterpret_cast<const float2*>(&b1[n * 256 + h0]);
    const float2 bbr0 = *reinterpret_cast<const float2*>(&b1[n * 256 + 128 + h0]);
    const float2 ba1  = *reinterpret_cast<const float2*>(&b1[n * 256 + h0 + 8]);
    const float2 bbr1 = *reinterpret_cast<const float2*>(&b1[n * 256 + 136 + h0]);

    // W2 fp16 B-fragment (k16 x n8, only n=0,1 real): lane (lr,q):
    //   b0 = {W2[16w+2q][lr], W2[16w+2q+1][lr]},  b1 = same with k+8
    uint32_t w2b0 = 0, w2b1 = 0;
    if (lr < 2) {
        const float* W2g = w2 + n * 256;
        const int k0 = 16 * w + 2 * q;
        w2b0 = pack16(W2g[k0 * 2 + lr],       W2g[(k0 + 1) * 2 + lr]);
        w2b1 = pack16(W2g[(k0 + 8) * 2 + lr], W2g[(k0 + 9) * 2 + lr]);
    }

    const float* W1g = w1 + (size_t)n * (MEM * HID);
    #pragma unroll
    for (int i = 0; i < 8; i++) {
        const int t  = tid + i * 256;
        const int c4 = t & 63;
        const int k  = t >> 6;
        cp16(sbase + OFF_W1S + (k * W1S_STRIDE + 4 * c4) * 4, W1g + k * HID + 4 * c4);
    }
    asm volatile("cp.async.commit_group;");

    // X: 4 x LDG.128 per thread -> fp16 fragments
    const float* Xg = state + (size_t)n * MEM;
    #pragma unroll
    for (int i = 0; i < 4; i++) {
        const int t    = tid + i * 256;
        const int s    = t & 7;          // float4 index in row (k0 = 4s)
        const int brow = t >> 3;         // batch row
        const float4 v = *reinterpret_cast<const float4*>(Xg + (size_t)brow * (NN * MEM) + 4 * s);
        const int p0   = 2 * s;
        const int q0   = p0 & 3;
        const int reg2 = (p0 >> 2) & 1;
        const int ks   = p0 >> 3;
        const int flr  = brow & 7;
        const int reg  = ((brow >> 3) & 1) + 2 * reg2;
        const int m    = brow >> 4;
        const int base = ((m * 2 + ks) * 32 + flr * 4) * 4 + reg;
        XF[base + q0 * 4]       = pack16(v.x, v.y);
        XF[base + (q0 + 1) * 4] = pack16(v.z, v.w);
    }

    // halved gate biases (0.5 folded into gate path; exact power-of-2 scaling)
    const float2 bb0 = make_float2(0.5f * bbr0.x, 0.5f * bbr0.y);
    const float2 bb1 = make_float2(0.5f * bbr1.x, 0.5f * bbr1.y);

    asm volatile("cp.async.wait_group 0;");
    __syncthreads();

    // ---------------- Build W1 fp16 fragments (gate side pre-scaled by 0.5) ----------------
    uint32_t BA[2][2][2], BB[2][2][2];
    #pragma unroll
    for (int p = 0; p < 2; p++) {
        const int colA = (2 * w + p) * 8 + lr;
        const int colB = colA + 128;
        #pragma unroll
        for (int ks = 0; ks < 2; ks++) {
            #pragma unroll
            for (int r = 0; r < 2; r++) {
                const int k = ks * 16 + r * 8 + 2 * q;
                BA[p][ks][r] = pack16(W1s[k * W1S_STRIDE + colA], W1s[(k + 1) * W1S_STRIDE + colA]);
                BB[p][ks][r] = pack16(0.5f * W1s[k * W1S_STRIDE + colB],
                                      0.5f * W1s[(k + 1) * W1S_STRIDE + colB]);
            }
        }
    }

    // ---------------- Mainloop over 8 M-tiles ----------------
    float* myPart = part + w * 256;
    #pragma unroll
    for (int m = 0; m < 8; m++) {
        const uint4 A0 = *reinterpret_cast<const uint4*>(&XF[((m * 2 + 0) * 32 + lane) * 4]);
        const uint4 A1 = *reinterpret_cast<const uint4*>(&XF[((m * 2 + 1) * 32 + lane) * 4]);

        uint32_t Ga0, Ga1, Ga2, Ga3;   // GLU output packed as GEMM2 A-fragment
        {
            float Ca[4] = {ba0.x, ba0.y, ba0.x, ba0.y};
            float Cb[4] = {bb0.x, bb0.y, bb0.x, bb0.y};
            mma_f16(Ca, A0.x, A0.y, A0.z, A0.w, BA[0][0][0], BA[0][0][1]);
            mma_f16(Cb, A0.x, A0.y, A0.z, A0.w, BB[0][0][0], BB[0][0][1]);
            mma_f16(Ca, A1.x, A1.y, A1.z, A1.w, BA[0][1][0], BA[0][1][1]);
            mma_f16(Cb, A1.x, A1.y, A1.z, A1.w, BB[0][1][0], BB[0][1][1]);
            const float g0 = Ca[0] * sigmoid_from_half(Cb[0]);
            const float g1 = Ca[1] * sigmoid_from_half(Cb[1]);
            const float g2 = Ca[2] * sigmoid_from_half(Cb[2]);
            const float g3 = Ca[3] * sigmoid_from_half(Cb[3]);
            Ga0 = pack16(g0, g1);      // (row lr,   k=2q,2q+1)
            Ga1 = pack16(g2, g3);      // (row lr+8, k=2q,2q+1)
        }
        {
            float Ca[4] = {ba1.x, ba1.y, ba1.x, ba1.y};
            float Cb[4] = {bb1.x, bb1.y, bb1.x, bb1.y};
            mma_f16(Ca, A0.x, A0.y, A0.z, A0.w, BA[1][0][0], BA[1][0][1]);
            mma_f16(Cb, A0.x, A0.y, A0.z, A0.w, BB[1][0][0], BB[1][0][1]);
            mma_f16(Ca, A1.x, A1.y, A1.z, A1.w, BA[1][1][0], BA[1][1][1]);
            mma_f16(Cb, A1.x, A1.y, A1.z, A1.w, BB[1][1][0], BB[1][1][1]);
            const float g0 = Ca[0] * sigmoid_from_half(Cb[0]);
            const float g1 = Ca[1] * sigmoid_from_half(Cb[1]);
            const float g2 = Ca[2] * sigmoid_from_half(Cb[2]);
            const float g3 = Ca[3] * sigmoid_from_half(Cb[3]);
            Ga2 = pack16(g0, g1);      // (row lr,   k=8+2q,+1)
            Ga3 = pack16(g2, g3);      // (row lr+8, k=8+2q,+1)
        }

        // GEMM2 as one MMA: D(16x8) = G(16x16) x W2frag(16x8); cols 0,1 real.
        float d[4];
        mma_f16_zc(d, Ga0, Ga1, Ga2, Ga3, w2b0, w2b1);

        // lanes q==0 hold (row lr: n=0,1) and (row lr+8: n=0,1) complete
        if (q == 0) {
            const int row = m * 16 + lr;
            *reinterpret_cast<float2*>(&myPart[row * 2])       = make_float2(d[0], d[1]);
            *reinterpret_cast<float2*>(&myPart[(row + 8) * 2]) = make_float2(d[2], d[3]);
        }
    }

    __syncthreads();

    // ---------------- Final: sum 8 warp partials (f32x2), GLU2 (precise), /T, store ----------------
    if (tid < 128) {
        uint64_t acc;
        {
            const float2 b2v = *reinterpret_cast<const float2*>(&b2[n * 2]);
            asm("mov.b64 %0, {%1, %2};" : "=l"(acc) : "f"(b2v.x), "f"(b2v.y));
        }
        #pragma unroll
        for (int ww = 0; ww < 8; ww++) {
            const uint64_t pv = *reinterpret_cast<const uint64_t*>(&part[ww * 256 + tid * 2]);
            asm("add.rn.f32x2 %0, %0, %1;" : "+l"(acc) : "l"(pv));
        }
        float y0, y1;
        asm("mov.b64 {%0, %1}, %2;" : "=f"(y0), "=f"(y1) : "l"(acc));
        out[(size_t)tid * NN + n] = (y0 * sigmoidf_acc(y1)) / Tg[0];
    }
}

extern "C" void kernel_launch(void* const* d_in, const int* in_sizes, int n_in,
                              void* d_out, int out_size) {
    const float* state = (const float*)d_in[0];
    const float* w1    = (const float*)d_in[1];
    const float* b1    = (const float*)d_in[2];
    const float* w2    = (const float*)d_in[3];
    const float* b2    = (const float*)d_in[4];
    const float* T     = (const float*)d_in[5];
    float* out = (float*)d_out;
    cudaFuncSetAttribute(nlm_kernel, cudaFuncAttributeMaxDynamicSharedMemorySize, SMEM_TOTAL);
    nlm_kernel<<<NN, 256, SMEM_TOTAL>>>(state, w1, b1, w2, b2, T, out);
}